// round 15
// baseline (speedup 1.0000x reference)
#include <cuda_runtime.h>
#include <cuda_fp16.h>
#include <cstdint>

#define N_NODE 100000        // N_USER == N_ITEM == 100000
#define NEDGE  1000000
#define C      128
#define CC     (C * C)
#define NC     ((size_t)N_NODE * C)

// ---------------- device scratch (allowed: __device__ globals) ----------------
__device__ __align__(16) __half g_hu[NC];           // fp16 copy of x_user
__device__ __align__(16) __half g_hi[NC];           // fp16 copy of x_item
__device__ __align__(16) __half g_hxu[NC];          // layer-0 user output (fp16)
__device__ __align__(16) __half g_hxi[NC];          // layer-0 item output (fp16)
__device__ __align__(16) __half g_hagg[3][NC];      // gathered means (fp16)
__device__ __align__(16) int    g_cnt[3 * N_NODE];
__device__ __align__(16) float  g_wsum[2 * CC];     // Wr[l,1]+Wr[l,2] per layer
__device__ __align__(16) int    g_rowptr[3 * (N_NODE + 1)];
__device__ __align__(16) int    g_colidx[3 * NEDGE];
__device__ __align__(16) int    g_cur[3 * N_NODE];

// ---------------- utility kernels ----------------
// fp32 -> fp16 copies of both feature matrices + zero cnt/cur (fused)
__global__ void cvt2h_zero_k(const float4* __restrict__ xu, const float4* __restrict__ xi,
                             uint2* __restrict__ hu, uint2* __restrict__ hi, long n4,
                             int4* __restrict__ z0, int4* __restrict__ z1, long nz4) {
    long i = (long)blockIdx.x * blockDim.x + threadIdx.x;
    long st = (long)gridDim.x * blockDim.x;
    for (long j = i; j < n4; j += st) {
        float4 a = xu[j];
        uint2 w;
        *(__half2*)&w.x = __floats2half2_rn(a.x, a.y);
        *(__half2*)&w.y = __floats2half2_rn(a.z, a.w);
        hu[j] = w;
        float4 b = xi[j];
        *(__half2*)&w.x = __floats2half2_rn(b.x, b.y);
        *(__half2*)&w.y = __floats2half2_rn(b.z, b.w);
        hi[j] = w;
    }
    int4 z = make_int4(0, 0, 0, 0);
    for (long j = i; j < nz4; j += st) { z0[j] = z; z1[j] = z; }
}

// both layers' Wr[l,1]+Wr[l,2] in one launch
__global__ void addW2_k(const float* __restrict__ Wr, float* __restrict__ o, int n) {
    int l = blockIdx.y;
    const float* a = Wr + (size_t)(l * 3 + 1) * CC;
    const float* b = Wr + (size_t)(l * 3 + 2) * CC;
    float* oo = o + (size_t)l * CC;
    int i = blockIdx.x * blockDim.x + threadIdx.x;
    if (i < n) oo[i] = a[i] + b[i];
}

// all 3 edge types in one launch: blockIdx.y selects type
__global__ void count3_k(const int* __restrict__ d0, const int* __restrict__ d1,
                         const int* __restrict__ d2, int* __restrict__ cnt, int E) {
    const int* dst = (blockIdx.y == 0) ? d0 : (blockIdx.y == 1) ? d1 : d2;
    int* c = cnt + blockIdx.y * N_NODE;
    int i = blockIdx.x * blockDim.x + threadIdx.x;
    int st = gridDim.x * blockDim.x;
    for (; i < E; i += st) atomicAdd(c + dst[i], 1);
}

__global__ void fill3_k(const int* __restrict__ e0, const int* __restrict__ e1,
                        const int* __restrict__ e2, const int* __restrict__ rowptr,
                        int* __restrict__ cur, int* __restrict__ col, int E) {
    const int* ei = (blockIdx.y == 0) ? e0 : (blockIdx.y == 1) ? e1 : e2;
    const int* rp = rowptr + blockIdx.y * (N_NODE + 1);
    int* cu = cur + blockIdx.y * N_NODE;
    int* co = col + blockIdx.y * NEDGE;
    int i = blockIdx.x * blockDim.x + threadIdx.x;
    int st = gridDim.x * blockDim.x;
    for (; i < E; i += st) {
        int s = ei[i];
        int d = ei[E + i];
        int pos = rp[d] + atomicAdd(cu + d, 1);
        co[pos] = s;
    }
}

// exclusive scan of one edge type's counts -> rowptr. One block per type.
#define SCAN_T 1024
__global__ void __launch_bounds__(SCAN_T) scan_k(const int* __restrict__ cnt,
                                                 int* __restrict__ rowptr) {
    int type = blockIdx.x;
    const int* c = cnt + type * N_NODE;
    int* rp = rowptr + type * (N_NODE + 1);
    __shared__ int part[SCAN_T];
    int t = threadIdx.x;
    const int chunk = (N_NODE + SCAN_T - 1) / SCAN_T;   // 98
    int beg = t * chunk;
    int end = beg + chunk; if (end > N_NODE) end = N_NODE;
    int s = 0;
    for (int i = beg; i < end; ++i) s += c[i];
    part[t] = s;
    __syncthreads();
    for (int off = 1; off < SCAN_T; off <<= 1) {
        int v = (t >= off) ? part[t - off] : 0;
        __syncthreads();
        part[t] += v;
        __syncthreads();
    }
    int prefix = (t == 0) ? 0 : part[t - 1];
    for (int i = beg; i < end; ++i) {
        rp[i] = prefix;
        prefix += c[i];
    }
    if (t == SCAN_T - 1) rp[N_NODE] = prefix;
}

// ---------------- CSR gather-mean body (fp16 in / fp16 out) ----------------
__device__ __forceinline__ void gather_body(
    const __half* __restrict__ x, const int* __restrict__ rp,
    const int* __restrict__ ci, __half* __restrict__ out, int n,
    int localBlock, int numBlocks)
{
    int lane = threadIdx.x & 31;
    int w = (localBlock * 256 + (int)threadIdx.x) >> 5;
    int nw = (numBlocks * 256) >> 5;
    for (int node = w; node < n; node += nw) {
        int beg = __ldg(rp + node);
        int end = __ldg(rp + node + 1);
        float4 v0 = make_float4(0.f, 0.f, 0.f, 0.f);
        float4 v1 = v0, v2 = v0, v3 = v0;
        int j = beg;
        for (; j + 3 < end; j += 4) {
            int s0 = __ldg(ci + j);
            int s1 = __ldg(ci + j + 1);
            int s2 = __ldg(ci + j + 2);
            int s3 = __ldg(ci + j + 3);
            uint2 a = __ldg((const uint2*)(x + (size_t)s0 * C) + lane);
            uint2 b = __ldg((const uint2*)(x + (size_t)s1 * C) + lane);
            uint2 c = __ldg((const uint2*)(x + (size_t)s2 * C) + lane);
            uint2 d = __ldg((const uint2*)(x + (size_t)s3 * C) + lane);
            float2 f;
            f = __half22float2(*(__half2*)&a.x); v0.x += f.x; v0.y += f.y;
            f = __half22float2(*(__half2*)&a.y); v0.z += f.x; v0.w += f.y;
            f = __half22float2(*(__half2*)&b.x); v1.x += f.x; v1.y += f.y;
            f = __half22float2(*(__half2*)&b.y); v1.z += f.x; v1.w += f.y;
            f = __half22float2(*(__half2*)&c.x); v2.x += f.x; v2.y += f.y;
            f = __half22float2(*(__half2*)&c.y); v2.z += f.x; v2.w += f.y;
            f = __half22float2(*(__half2*)&d.x); v3.x += f.x; v3.y += f.y;
            f = __half22float2(*(__half2*)&d.y); v3.z += f.x; v3.w += f.y;
        }
        for (; j < end; ++j) {
            int s0 = __ldg(ci + j);
            uint2 a = __ldg((const uint2*)(x + (size_t)s0 * C) + lane);
            float2 f;
            f = __half22float2(*(__half2*)&a.x); v0.x += f.x; v0.y += f.y;
            f = __half22float2(*(__half2*)&a.y); v0.z += f.x; v0.w += f.y;
        }
        int cdeg = end - beg;
        float sc = 1.0f / (float)(cdeg > 1 ? cdeg : 1);
        float r0 = (v0.x + v1.x + v2.x + v3.x) * sc;
        float r1 = (v0.y + v1.y + v2.y + v3.y) * sc;
        float r2 = (v0.z + v1.z + v2.z + v3.z) * sc;
        float r3 = (v0.w + v1.w + v2.w + v3.w) * sc;
        uint2 wv;
        *(__half2*)&wv.x = __floats2half2_rn(r0, r1);
        *(__half2*)&wv.y = __floats2half2_rn(r2, r3);
        *((uint2*)(out + (size_t)node * C) + lane) = wv;
    }
}

// standalone gather: types [type0, type0+gridDim.y) via blockIdx.y
__global__ void __launch_bounds__(256) gather3h_k(
    const __half* __restrict__ x0, const __half* __restrict__ x1,
    const __half* __restrict__ x2,
    const int* __restrict__ rowptr, const int* __restrict__ colidx,
    __half* __restrict__ agg, int n, int type0)
{
    int type = type0 + blockIdx.y;
    const __half* x = (type == 0) ? x0 : (type == 1) ? x1 : x2;
    gather_body(x, rowptr + type * (N_NODE + 1), colidx + (size_t)type * NEDGE,
                agg + (size_t)type * NC, n, blockIdx.x, gridDim.x);
}

// ================ fp16 mma.sync GEMM (fp32 accum) + bias + LN + ReLU ================
// CTA tile 128x128, K=128; 8 warps 2M x 4N; warp 64x32 via m16n8k16.f32.f16.f16.f32.
// A frag word (m, p=k>>1): lane=(m&7)*4+(p&3), slot=((m>>3)&1)|(((p>>2)&1)<<1);
//   idx32 = ks*1028 + mt*128 + lane*4 + slot.          (ks=k>>4, mt=m>>4)
// B frag word (n, p): lane=(n&7)*4+(p&3), slot=(p>>2)&1;
//   idx32 = (ks*16+nt)*66 + lane*2 + slot.             (nt=n>>3)

#define MMA_F16(d, a, b)                                                        \
    asm volatile("mma.sync.aligned.m16n8k16.row.col.f32.f16.f16.f32 "           \
                 "{%0,%1,%2,%3}, {%4,%5,%6,%7}, {%8,%9}, {%0,%1,%2,%3};"        \
                 : "+f"((d)[0]), "+f"((d)[1]), "+f"((d)[2]), "+f"((d)[3])       \
                 : "r"((a).x), "r"((a).y), "r"((a).z), "r"((a).w),              \
                   "r"((b).x), "r"((b).y))

// SMEM layout (bytes)
#define SM_A      0          // 8 ks x 1028 uint32 = 32896 B
#define SM_B      32896      // 8 ks x 16 nt x 66 uint32 = 33792 B -> ends 66688
#define SM_PART   66688      // 128 rows x 4 warps x float2 = 4096
#define SM_STAT   70784      // 128 x float2 = 1024
#define SM_BIAS   71808      // 128 f32
#define SM_LNW    72320
#define SM_LNB    72832
#define GEMM_SMEM 73344

#define GEMM_GRID 782        // ceil(100000 / 128)

__device__ __forceinline__ void stage_A16(uint32_t* sA, const __half* __restrict__ A,
                                          int nodeBase, int N, int t)
{
#pragma unroll
    for (int i = 0; i < 16; ++i) {
        int f = t + i * 256;              // m = f>>5, k4 = f&31
        int m = f >> 5, k4 = f & 31;
        int node = nodeBase + m;
        uint2 v = (node < N) ? __ldg((const uint2*)(A + (size_t)node * C) + k4)
                             : make_uint2(0u, 0u);
        int ks = k4 >> 2;
        int mt = m >> 4;
        uint32_t wrd[2] = {v.x, v.y};
#pragma unroll
        for (int j = 0; j < 2; ++j) {
            int p = 2 * k4 + j;
            int lane = (m & 7) * 4 + (p & 3);
            int slot = ((m >> 3) & 1) | ((((p >> 2) & 1)) << 1);
            sA[ks * 1028 + mt * 128 + lane * 4 + slot] = wrd[j];
        }
    }
}

__device__ __forceinline__ void stage_B16(uint32_t* sB, const float* __restrict__ W, int t)
{
#pragma unroll
    for (int i = 0; i < 8; ++i) {
        int f = t + i * 256;              // kp = f>>5 (0..63), n4 = f&31
        int kp = f >> 5, n4 = f & 31;
        float4 w0 = __ldg((const float4*)W + (2 * kp) * 32 + n4);
        float4 w1 = __ldg((const float4*)W + (2 * kp + 1) * 32 + n4);
        float a0[4] = {w0.x, w0.y, w0.z, w0.w};
        float a1[4] = {w1.x, w1.y, w1.z, w1.w};
        int ks = kp >> 3;
        int slot = (kp >> 2) & 1;
        int lane_k = kp & 3;
#pragma unroll
        for (int e = 0; e < 4; ++e) {
            int n = 4 * n4 + e;
            int nt = n >> 3;
            int lane = (n & 7) * 4 + lane_k;
            uint32_t wrd;
            *(__half2*)&wrd = __floats2half2_rn(a0[e], a1[e]);
            sB[(ks * 16 + nt) * 66 + lane * 2 + slot] = wrd;
        }
    }
}

template <int NTERMS, bool HOUT>
__device__ __forceinline__ void gemm_body(
    const __half* __restrict__ A0, const float* __restrict__ W0,
    const __half* __restrict__ A1, const float* __restrict__ W1,
    const __half* __restrict__ A2, const float* __restrict__ W2,
    const float* __restrict__ bias0, const float* __restrict__ bias1,
    const float* __restrict__ lnw, const float* __restrict__ lnb,
    void* __restrict__ outp, int N, int blockM)
{
    extern __shared__ char smem[];
    uint32_t* sA = (uint32_t*)(smem + SM_A);
    uint32_t* sB = (uint32_t*)(smem + SM_B);
    float2* sPart = (float2*)(smem + SM_PART);
    float2* sStat = (float2*)(smem + SM_STAT);
    float* sBias  = (float*)(smem + SM_BIAS);
    float* sLnw   = (float*)(smem + SM_LNW);
    float* sLnb   = (float*)(smem + SM_LNB);

    const int t = threadIdx.x;
    const int warp = t >> 5;
    const int lane = t & 31;
    const int wm = warp >> 2;
    const int wn = warp & 3;
    const int nodeBase = blockM * 128;

    if (t < 128) {
        float b = bias0 ? __ldg(bias0 + t) : 0.f;
        if (bias1) b += __ldg(bias1 + t);
        sBias[t] = b;
        sLnw[t] = __ldg(lnw + t);
        sLnb[t] = __ldg(lnb + t);
    }

    const __half* As[3] = {A0, A1, A2};
    const float*  Ws[3] = {W0, W1, W2};

    float acc[4][4][4];
#pragma unroll
    for (int a = 0; a < 4; ++a)
#pragma unroll
        for (int b = 0; b < 4; ++b)
#pragma unroll
            for (int c = 0; c < 4; ++c) acc[a][b][c] = 0.f;

    const uint4* sA4 = (const uint4*)sA;
    const uint2* sB2 = (const uint2*)sB;

#pragma unroll 1
    for (int term = 0; term < NTERMS; ++term) {
        if (term > 0) __syncthreads();
        stage_A16(sA, As[term], nodeBase, N, t);
        stage_B16(sB, Ws[term], t);
        __syncthreads();

#pragma unroll 1
        for (int ks = 0; ks < 8; ++ks) {
            uint4 af[4];
            uint2 bf[4];
#pragma unroll
            for (int mt = 0; mt < 4; ++mt)
                af[mt] = sA4[ks * 257 + (wm * 4 + mt) * 32 + lane];
#pragma unroll
            for (int nt = 0; nt < 4; ++nt)
                bf[nt] = sB2[(ks * 16 + wn * 4 + nt) * 33 + lane];
#pragma unroll
            for (int mt = 0; mt < 4; ++mt)
#pragma unroll
                for (int nt = 0; nt < 4; ++nt)
                    MMA_F16(acc[mt][nt], af[mt], bf[nt]);
        }
    }

    // epilogue: bias + LayerNorm + ReLU
#pragma unroll
    for (int mt = 0; mt < 4; ++mt) {
#pragma unroll
        for (int hi = 0; hi < 2; ++hi) {
            float s = 0.f, q = 0.f;
#pragma unroll
            for (int nt = 0; nt < 4; ++nt) {
#pragma unroll
                for (int e = 0; e < 2; ++e) {
                    int col = (wn * 4 + nt) * 8 + (lane & 3) * 2 + e;
                    float v = acc[mt][nt][hi * 2 + e] + sBias[col];
                    s += v; q += v * v;
                }
            }
            s += __shfl_xor_sync(0xffffffffu, s, 1);
            q += __shfl_xor_sync(0xffffffffu, q, 1);
            s += __shfl_xor_sync(0xffffffffu, s, 2);
            q += __shfl_xor_sync(0xffffffffu, q, 2);
            if ((lane & 3) == 0) {
                int row = (wm * 4 + mt) * 16 + hi * 8 + (lane >> 2);
                sPart[row * 4 + wn] = make_float2(s, q);
            }
        }
    }
    __syncthreads();
    if (t < 128) {
        float2 p0 = sPart[t * 4 + 0], p1 = sPart[t * 4 + 1];
        float2 p2 = sPart[t * 4 + 2], p3 = sPart[t * 4 + 3];
        float s = p0.x + p1.x + p2.x + p3.x;
        float q = p0.y + p1.y + p2.y + p3.y;
        float mu = s * (1.0f / C);
        float var = q * (1.0f / C) - mu * mu;
        sStat[t] = make_float2(mu, rsqrtf(var + 1e-5f));
    }
    __syncthreads();

#pragma unroll
    for (int mt = 0; mt < 4; ++mt) {
#pragma unroll
        for (int hi = 0; hi < 2; ++hi) {
            int row = (wm * 4 + mt) * 16 + hi * 8 + (lane >> 2);
            int node = nodeBase + row;
            if (node < N) {
                float2 st = sStat[row];
#pragma unroll
                for (int nt = 0; nt < 4; ++nt) {
                    int col = (wn * 4 + nt) * 8 + (lane & 3) * 2;
                    float v0 = acc[mt][nt][hi * 2 + 0] + sBias[col];
                    float v1 = acc[mt][nt][hi * 2 + 1] + sBias[col + 1];
                    float o0 = fmaxf((v0 - st.x) * st.y * sLnw[col]     + sLnb[col],     0.f);
                    float o1 = fmaxf((v1 - st.x) * st.y * sLnw[col + 1] + sLnb[col + 1], 0.f);
                    if (HOUT) {
                        __half* o = (__half*)outp + (size_t)node * C + col;
                        *(__half2*)o = __floats2half2_rn(o0, o1);
                    } else {
                        float* o = (float*)outp + (size_t)node * C + col;
                        *(float2*)o = make_float2(o0, o1);
                    }
                }
            }
        }
    }
}

// plain GEMM kernel
template <int NTERMS, bool HOUT>
__global__ void __launch_bounds__(256, 2) gemm_mma(
    const __half* __restrict__ A0, const float* __restrict__ W0,
    const __half* __restrict__ A1, const float* __restrict__ W1,
    const __half* __restrict__ A2, const float* __restrict__ W2,
    const float* __restrict__ bias0, const float* __restrict__ bias1,
    const float* __restrict__ lnw, const float* __restrict__ lnb,
    void* __restrict__ outp, int N)
{
    gemm_body<NTERMS, HOUT>(A0, W0, A1, W1, A2, W2, bias0, bias1,
                            lnw, lnb, outp, N, blockIdx.x);
}

// FUSED1: blocks [0, GEMM_GRID) = 2-term GEMM (item l0, fp16 out);
//         blocks beyond = gathers for types 1 and 2 (layer 0).
#define FUSE_GB 2048   // gather blocks per type
__global__ void __launch_bounds__(256, 2) fused_gemm_gather_k(
    const __half* __restrict__ A0, const float* __restrict__ W0,
    const __half* __restrict__ A1, const float* __restrict__ W1,
    const float* __restrict__ bias0,
    const float* __restrict__ lnw, const float* __restrict__ lnb,
    void* __restrict__ outp, int N,
    const __half* __restrict__ xg1, const __half* __restrict__ xg2,
    const int* __restrict__ rowptr, const int* __restrict__ colidx,
    __half* __restrict__ agg)
{
    if ((int)blockIdx.x < GEMM_GRID) {
        gemm_body<2, true>(A0, W0, A1, W1, nullptr, nullptr, bias0, nullptr,
                           lnw, lnb, outp, N, blockIdx.x);
    } else {
        int gb = blockIdx.x - GEMM_GRID;
        int type = 1 + gb / FUSE_GB;
        int lb = gb % FUSE_GB;
        const __half* x = (type == 1) ? xg1 : xg2;
        gather_body(x, rowptr + type * (N_NODE + 1), colidx + (size_t)type * NEDGE,
                    agg + (size_t)type * NC, N, lb, FUSE_GB);
    }
}

// FUSED2: blocks [0, GEMM_GRID) = item GEMM l1; [GEMM_GRID, 2*GEMM_GRID) = user GEMM l1.
__global__ void __launch_bounds__(256, 2) fused_gemm2_k(
    // item (2-term)
    const __half* __restrict__ iA0, const float* __restrict__ iW0,
    const __half* __restrict__ iA1, const float* __restrict__ iW1,
    const float* __restrict__ ib0,
    const float* __restrict__ ilnw, const float* __restrict__ ilnb,
    float* __restrict__ iout,
    // user (3-term)
    const __half* __restrict__ uA0, const float* __restrict__ uW0,
    const __half* __restrict__ uA1, const float* __restrict__ uW1,
    const __half* __restrict__ uA2, const float* __restrict__ uW2,
    const float* __restrict__ ub0, const float* __restrict__ ub1,
    const float* __restrict__ ulnw, const float* __restrict__ ulnb,
    float* __restrict__ uout, int N)
{
    if ((int)blockIdx.x < GEMM_GRID) {
        gemm_body<2, false>(iA0, iW0, iA1, iW1, nullptr, nullptr, ib0, nullptr,
                            ilnw, ilnb, iout, N, blockIdx.x);
    } else {
        gemm_body<3, false>(uA0, uW0, uA1, uW1, uA2, uW2, ub0, ub1,
                            ulnw, ulnb, uout, N, blockIdx.x - GEMM_GRID);
    }
}

// ---------------- host launcher (single stream) ----------------
extern "C" void kernel_launch(void* const* d_in, const int* in_sizes, int n_in,
                              void* d_out, int out_size)
{
    const float* x_user = (const float*)d_in[0];
    const float* x_item = (const float*)d_in[1];
    const int*   ei_ui  = (const int*)d_in[2];
    const int*   ei_iu  = (const int*)d_in[3];
    const int*   ei_uu  = (const int*)d_in[4];
    const float* Wl     = (const float*)d_in[5];
    const float* bl     = (const float*)d_in[6];
    const float* Wr     = (const float*)d_in[7];
    const float* ln_w   = (const float*)d_in[8];
    const float* ln_b   = (const float*)d_in[9];
    float* out = (float*)d_out;

    void *phu_, *phi_, *phxu_, *phxi_, *phagg_, *pcnt_, *pws_, *prp_, *pci_, *pcur_;
    cudaGetSymbolAddress(&phu_, g_hu);
    cudaGetSymbolAddress(&phi_, g_hi);
    cudaGetSymbolAddress(&phxu_, g_hxu);
    cudaGetSymbolAddress(&phxi_, g_hxi);
    cudaGetSymbolAddress(&phagg_, g_hagg);
    cudaGetSymbolAddress(&pcnt_, g_cnt);
    cudaGetSymbolAddress(&pws_, g_wsum);
    cudaGetSymbolAddress(&prp_, g_rowptr);
    cudaGetSymbolAddress(&pci_, g_colidx);
    cudaGetSymbolAddress(&pcur_, g_cur);
    __half* phu  = (__half*)phu_;
    __half* phi  = (__half*)phi_;
    __half* phxu = (__half*)phxu_;
    __half* phxi = (__half*)phxi_;
    __half* phagg = (__half*)phagg_;
    int*   pcnt = (int*)pcnt_;
    float* pws  = (float*)pws_;
    int*   prp  = (int*)prp_;
    int*   pci  = (int*)pci_;
    int*   pcur = (int*)pcur_;

    cudaFuncSetAttribute((const void*)gemm_mma<3, true>,
                         cudaFuncAttributeMaxDynamicSharedMemorySize, GEMM_SMEM);
    cudaFuncSetAttribute((const void*)fused_gemm_gather_k,
                         cudaFuncAttributeMaxDynamicSharedMemorySize, GEMM_SMEM);
    cudaFuncSetAttribute((const void*)fused_gemm2_k,
                         cudaFuncAttributeMaxDynamicSharedMemorySize, GEMM_SMEM);

    const int GATHER_BLOCKS = 4096;

    // 1. fp16 copies + zero cnt/cur
    cvt2h_zero_k<<<2048, 256>>>((const float4*)x_user, (const float4*)x_item,
                                (uint2*)phu, (uint2*)phi, (long)(NC / 4),
                                (int4*)pcnt, (int4*)pcur, (long)(3 * N_NODE) / 4);
    // 2. wsum both layers
    addW2_k<<<dim3((CC + 255) / 256, 2), 256>>>(Wr, pws, CC);
    // 3-5. CSR build
    count3_k<<<dim3(1024, 3), 256>>>(ei_ui + NEDGE, ei_iu + NEDGE, ei_uu + NEDGE,
                                     pcnt, NEDGE);
    scan_k<<<3, SCAN_T>>>(pcnt, prp);
    fill3_k<<<dim3(1024, 3), 256>>>(ei_ui, ei_iu, ei_uu, prp, pcur, pci, NEDGE);

    // ---------------- layer 0 ----------------
    // 6. gather type 0 (user->item means)
    gather3h_k<<<dim3(GATHER_BLOCKS, 1), 256>>>(phu, phi, phu, prp, pci, phagg,
                                                N_NODE, 0);
    // 7. FUSED: item GEMM l0 (agg0,phi -> phxi) + gathers types 1,2 (phi/phu -> agg1,2)
    fused_gemm_gather_k<<<GEMM_GRID + 2 * FUSE_GB, 256, GEMM_SMEM>>>(
        phagg + 0 * NC, Wl + 0 * CC,
        phi,            Wr + 0 * CC,
        bl + 0 * C, ln_w + 1 * C, ln_b + 1 * C,
        phxi, N_NODE,
        phi, phu, prp, pci, phagg);
    // 8. user GEMM l0 -> phxu
    gemm_mma<3, true><<<GEMM_GRID, 256, GEMM_SMEM>>>(
        phagg + 1 * NC, Wl + 1 * CC,
        phagg + 2 * NC, Wl + 2 * CC,
        phu,            pws + 0 * CC,
        bl + 1 * C, bl + 2 * C, ln_w + 0 * C, ln_b + 0 * C,
        phxu, N_NODE);

    // ---------------- layer 1 ----------------
    // 9. gather all 3 types (phxu/phxi -> agg)
    gather3h_k<<<dim3(GATHER_BLOCKS, 3), 256>>>(phxu, phxi, phxu, prp, pci, phagg,
                                                N_NODE, 0);
    // 10. FUSED: item GEMM l1 -> out[NC:], user GEMM l1 -> out[:NC]
    fused_gemm2_k<<<2 * GEMM_GRID, 256, GEMM_SMEM>>>(
        phagg + 0 * NC, Wl + (size_t)(1 * 3 + 0) * CC,
        phxi,           Wr + (size_t)(1 * 3 + 0) * CC,
        bl + (size_t)(1 * 3 + 0) * C,
        ln_w + (size_t)(1 * 2 + 1) * C, ln_b + (size_t)(1 * 2 + 1) * C,
        out + NC,
        phagg + 1 * NC, Wl + (size_t)(1 * 3 + 1) * CC,
        phagg + 2 * NC, Wl + (size_t)(1 * 3 + 2) * CC,
        phxu,           pws + 1 * CC,
        bl + (size_t)(1 * 3 + 1) * C, bl + (size_t)(1 * 3 + 2) * C,
        ln_w + (size_t)(1 * 2 + 0) * C, ln_b + (size_t)(1 * 2 + 0) * C,
        out, N_NODE);
}

// round 16
// speedup vs baseline: 1.4224x; 1.4224x over previous
#include <cuda_runtime.h>
#include <cuda_fp16.h>
#include <cstdint>

#define N_NODE 100000        // N_USER == N_ITEM == 100000
#define NEDGE  1000000
#define C      128
#define CC     (C * C)
#define NC     ((size_t)N_NODE * C)

// ---------------- device scratch (allowed: __device__ globals) ----------------
__device__ __align__(16) __half g_hu[NC];           // fp16 copy of x_user
__device__ __align__(16) __half g_hi[NC];           // fp16 copy of x_item
__device__ __align__(16) __half g_hxu[NC];          // layer-0 user output (fp16)
__device__ __align__(16) __half g_hxi[NC];          // layer-0 item output (fp16)
__device__ __align__(16) __half g_hagg[3][NC];      // gathered means (fp16)
__device__ __align__(16) int    g_cnt[3 * N_NODE];
__device__ __align__(16) float  g_wsum[2 * CC];     // Wr[l,1]+Wr[l,2] per layer
__device__ __align__(16) int    g_rowptr[3 * (N_NODE + 1)];
__device__ __align__(16) int    g_colidx[3 * NEDGE];
__device__ __align__(16) int    g_cur[3 * N_NODE];

#define SCHUNK 1024
#define SNB ((N_NODE + SCHUNK - 1) / SCHUNK)        // 98 chunks per type
__device__ __align__(16) int    g_bsum[3 * SNB];    // per-chunk sums
__device__ __align__(16) int    g_boff[3 * SNB];    // per-chunk exclusive offsets

// ---------------- utility kernels ----------------
// fp32 -> fp16 copies of both feature matrices + zero cnt/cur (fused)
__global__ void cvt2h_zero_k(const float4* __restrict__ xu, const float4* __restrict__ xi,
                             uint2* __restrict__ hu, uint2* __restrict__ hi, long n4,
                             int4* __restrict__ z0, int4* __restrict__ z1, long nz4) {
    long i = (long)blockIdx.x * blockDim.x + threadIdx.x;
    long st = (long)gridDim.x * blockDim.x;
    for (long j = i; j < n4; j += st) {
        float4 a = xu[j];
        uint2 w;
        *(__half2*)&w.x = __floats2half2_rn(a.x, a.y);
        *(__half2*)&w.y = __floats2half2_rn(a.z, a.w);
        hu[j] = w;
        float4 b = xi[j];
        *(__half2*)&w.x = __floats2half2_rn(b.x, b.y);
        *(__half2*)&w.y = __floats2half2_rn(b.z, b.w);
        hi[j] = w;
    }
    int4 z = make_int4(0, 0, 0, 0);
    for (long j = i; j < nz4; j += st) { z0[j] = z; z1[j] = z; }
}

// both layers' Wr[l,1]+Wr[l,2] in one launch
__global__ void addW2_k(const float* __restrict__ Wr, float* __restrict__ o, int n) {
    int l = blockIdx.y;
    const float* a = Wr + (size_t)(l * 3 + 1) * CC;
    const float* b = Wr + (size_t)(l * 3 + 2) * CC;
    float* oo = o + (size_t)l * CC;
    int i = blockIdx.x * blockDim.x + threadIdx.x;
    if (i < n) oo[i] = a[i] + b[i];
}

// all 3 edge types in one launch: blockIdx.y selects type
__global__ void count3_k(const int* __restrict__ d0, const int* __restrict__ d1,
                         const int* __restrict__ d2, int* __restrict__ cnt, int E) {
    const int* dst = (blockIdx.y == 0) ? d0 : (blockIdx.y == 1) ? d1 : d2;
    int* c = cnt + blockIdx.y * N_NODE;
    int i = blockIdx.x * blockDim.x + threadIdx.x;
    int st = gridDim.x * blockDim.x;
    for (; i < E; i += st) atomicAdd(c + dst[i], 1);
}

__global__ void fill3_k(const int* __restrict__ e0, const int* __restrict__ e1,
                        const int* __restrict__ e2, const int* __restrict__ rowptr,
                        int* __restrict__ cur, int* __restrict__ col, int E) {
    const int* ei = (blockIdx.y == 0) ? e0 : (blockIdx.y == 1) ? e1 : e2;
    const int* rp = rowptr + blockIdx.y * (N_NODE + 1);
    int* cu = cur + blockIdx.y * N_NODE;
    int* co = col + blockIdx.y * NEDGE;
    int i = blockIdx.x * blockDim.x + threadIdx.x;
    int st = gridDim.x * blockDim.x;
    for (; i < E; i += st) {
        int s = ei[i];
        int d = ei[E + i];
        int pos = rp[d] + atomicAdd(cu + d, 1);
        co[pos] = s;
    }
}

// ---------------- 3-phase parallel exclusive scan: cnt -> rowptr ----------------
// Phase A: per-chunk sums. grid (SNB, 3), 256 threads.
__global__ void __launch_bounds__(256) scanA_k(const int* __restrict__ cnt,
                                               int* __restrict__ bsum) {
    int type = blockIdx.y;
    const int* c = cnt + type * N_NODE;
    int base = blockIdx.x * SCHUNK;
    int s = 0;
    for (int i = threadIdx.x; i < SCHUNK; i += 256) {
        int idx = base + i;
        if (idx < N_NODE) s += __ldg(c + idx);
    }
#pragma unroll
    for (int o = 16; o > 0; o >>= 1) s += __shfl_xor_sync(0xffffffffu, s, o);
    __shared__ int ws[8];
    if ((threadIdx.x & 31) == 0) ws[threadIdx.x >> 5] = s;
    __syncthreads();
    if (threadIdx.x == 0) {
        int t = 0;
#pragma unroll
        for (int i = 0; i < 8; ++i) t += ws[i];
        bsum[type * SNB + blockIdx.x] = t;
    }
}

// Phase B: exclusive scan of SNB chunk sums per type; writes boff and rp[N_NODE].
__global__ void __launch_bounds__(128) scanB_k(const int* __restrict__ bsum,
                                               int* __restrict__ boff,
                                               int* __restrict__ rowptr) {
    int type = blockIdx.x;
    __shared__ int sh[128];
    int t = threadIdx.x;
    int v = (t < SNB) ? bsum[type * SNB + t] : 0;
    sh[t] = v;
    __syncthreads();
    for (int o = 1; o < 128; o <<= 1) {
        int u = (t >= o) ? sh[t - o] : 0;
        __syncthreads();
        sh[t] += u;
        __syncthreads();
    }
    if (t < SNB) boff[type * SNB + t] = sh[t] - v;   // exclusive
    if (t == SNB - 1) rowptr[type * (N_NODE + 1) + N_NODE] = sh[t];
}

// Phase C: in-chunk exclusive scan + chunk offset -> rowptr. grid (SNB, 3), 256 thr.
__global__ void __launch_bounds__(256) scanC_k(const int* __restrict__ cnt,
                                               const int* __restrict__ boff,
                                               int* __restrict__ rowptr) {
    int type = blockIdx.y;
    const int* c = cnt + type * N_NODE;
    int* rp = rowptr + type * (N_NODE + 1);
    int base = blockIdx.x * SCHUNK;
    int t = threadIdx.x;

    // each thread owns 4 consecutive elements
    int idx0 = base + t * 4;
    int e[4];
#pragma unroll
    for (int j = 0; j < 4; ++j)
        e[j] = (idx0 + j < N_NODE) ? __ldg(c + idx0 + j) : 0;
    int tsum = e[0] + e[1] + e[2] + e[3];

    // inclusive scan of tsum over 256 threads (warp shuffle + warp totals)
    int lane = t & 31, wid = t >> 5;
    int inc = tsum;
#pragma unroll
    for (int o = 1; o < 32; o <<= 1) {
        int u = __shfl_up_sync(0xffffffffu, inc, o);
        if (lane >= o) inc += u;
    }
    __shared__ int wtot[8];
    if (lane == 31) wtot[wid] = inc;
    __syncthreads();
    int wpre = 0;
#pragma unroll
    for (int i = 0; i < 8; ++i) wpre += (i < wid) ? wtot[i] : 0;
    int excl = wpre + inc - tsum + __ldg(boff + type * SNB + blockIdx.x);

#pragma unroll
    for (int j = 0; j < 4; ++j) {
        if (idx0 + j < N_NODE) rp[idx0 + j] = excl;
        excl += e[j];
    }
}

// ---------------- CSR gather-mean (fp16 in / fp16 out), types via blockIdx.y ----------
__global__ void __launch_bounds__(256) gather3h_k(
    const __half* __restrict__ x0, const __half* __restrict__ x1,
    const __half* __restrict__ x2,
    const int* __restrict__ rowptr, const int* __restrict__ colidx,
    __half* __restrict__ agg, int n)
{
    int type = blockIdx.y;
    const __half* x = (type == 0) ? x0 : (type == 1) ? x1 : x2;
    const int* rp = rowptr + type * (N_NODE + 1);
    const int* ci = colidx + (size_t)type * NEDGE;
    __half* out = agg + (size_t)type * NC;

    int lane = threadIdx.x & 31;
    int w = (blockIdx.x * blockDim.x + threadIdx.x) >> 5;
    int nw = (gridDim.x * blockDim.x) >> 5;
    for (int node = w; node < n; node += nw) {
        int beg = __ldg(rp + node);
        int end = __ldg(rp + node + 1);
        float4 v0 = make_float4(0.f, 0.f, 0.f, 0.f);
        float4 v1 = v0, v2 = v0, v3 = v0;
        int j = beg;
        for (; j + 3 < end; j += 4) {
            int s0 = __ldg(ci + j);
            int s1 = __ldg(ci + j + 1);
            int s2 = __ldg(ci + j + 2);
            int s3 = __ldg(ci + j + 3);
            uint2 a = __ldg((const uint2*)(x + (size_t)s0 * C) + lane);
            uint2 b = __ldg((const uint2*)(x + (size_t)s1 * C) + lane);
            uint2 c = __ldg((const uint2*)(x + (size_t)s2 * C) + lane);
            uint2 d = __ldg((const uint2*)(x + (size_t)s3 * C) + lane);
            float2 f;
            f = __half22float2(*(__half2*)&a.x); v0.x += f.x; v0.y += f.y;
            f = __half22float2(*(__half2*)&a.y); v0.z += f.x; v0.w += f.y;
            f = __half22float2(*(__half2*)&b.x); v1.x += f.x; v1.y += f.y;
            f = __half22float2(*(__half2*)&b.y); v1.z += f.x; v1.w += f.y;
            f = __half22float2(*(__half2*)&c.x); v2.x += f.x; v2.y += f.y;
            f = __half22float2(*(__half2*)&c.y); v2.z += f.x; v2.w += f.y;
            f = __half22float2(*(__half2*)&d.x); v3.x += f.x; v3.y += f.y;
            f = __half22float2(*(__half2*)&d.y); v3.z += f.x; v3.w += f.y;
        }
        for (; j < end; ++j) {
            int s0 = __ldg(ci + j);
            uint2 a = __ldg((const uint2*)(x + (size_t)s0 * C) + lane);
            float2 f;
            f = __half22float2(*(__half2*)&a.x); v0.x += f.x; v0.y += f.y;
            f = __half22float2(*(__half2*)&a.y); v0.z += f.x; v0.w += f.y;
        }
        int cdeg = end - beg;
        float sc = 1.0f / (float)(cdeg > 1 ? cdeg : 1);
        float r0 = (v0.x + v1.x + v2.x + v3.x) * sc;
        float r1 = (v0.y + v1.y + v2.y + v3.y) * sc;
        float r2 = (v0.z + v1.z + v2.z + v3.z) * sc;
        float r3 = (v0.w + v1.w + v2.w + v3.w) * sc;
        uint2 wv;
        *(__half2*)&wv.x = __floats2half2_rn(r0, r1);
        *(__half2*)&wv.y = __floats2half2_rn(r2, r3);
        *((uint2*)(out + (size_t)node * C) + lane) = wv;
    }
}

// ================ fp16 mma.sync GEMM (fp32 accum) + bias + LN + ReLU ================
// CTA tile 128x128, K=128; 8 warps 2M x 4N; warp 64x32 via m16n8k16.f32.f16.f16.f32.
// 2 CTAs/SM (73KB smem). A frag word (m, p=k>>1): lane=(m&7)*4+(p&3),
//   slot=((m>>3)&1)|(((p>>2)&1)<<1); idx32 = ks*1028 + mt*128 + lane*4 + slot.
// B frag word (n, p): lane=(n&7)*4+(p&3), slot=(p>>2)&1;
//   idx32 = (ks*16+nt)*66 + lane*2 + slot.   (ks=k>>4, mt=m>>4, nt=n>>3)

#define MMA_F16(d, a, b)                                                        \
    asm volatile("mma.sync.aligned.m16n8k16.row.col.f32.f16.f16.f32 "           \
                 "{%0,%1,%2,%3}, {%4,%5,%6,%7}, {%8,%9}, {%0,%1,%2,%3};"        \
                 : "+f"((d)[0]), "+f"((d)[1]), "+f"((d)[2]), "+f"((d)[3])       \
                 : "r"((a).x), "r"((a).y), "r"((a).z), "r"((a).w),              \
                   "r"((b).x), "r"((b).y))

// SMEM layout (bytes)
#define SM_A      0          // 8 ks x 1028 uint32 = 32896 B
#define SM_B      32896      // 8 ks x 16 nt x 66 uint32 = 33792 B -> ends 66688
#define SM_PART   66688      // 128 rows x 4 warps x float2 = 4096
#define SM_STAT   70784      // 128 x float2 = 1024
#define SM_BIAS   71808      // 128 f32
#define SM_LNW    72320
#define SM_LNB    72832
#define GEMM_SMEM 73344

#define GEMM_GRID 782        // ceil(100000 / 128)

__device__ __forceinline__ void stage_A16(uint32_t* sA, const __half* __restrict__ A,
                                          int nodeBase, int N, int t)
{
#pragma unroll
    for (int i = 0; i < 16; ++i) {
        int f = t + i * 256;              // m = f>>5, k4 = f&31
        int m = f >> 5, k4 = f & 31;
        int node = nodeBase + m;
        uint2 v = (node < N) ? __ldg((const uint2*)(A + (size_t)node * C) + k4)
                             : make_uint2(0u, 0u);
        int ks = k4 >> 2;
        int mt = m >> 4;
        uint32_t wrd[2] = {v.x, v.y};
#pragma unroll
        for (int j = 0; j < 2; ++j) {
            int p = 2 * k4 + j;
            int lane = (m & 7) * 4 + (p & 3);
            int slot = ((m >> 3) & 1) | ((((p >> 2) & 1)) << 1);
            sA[ks * 1028 + mt * 128 + lane * 4 + slot] = wrd[j];
        }
    }
}

__device__ __forceinline__ void stage_B16(uint32_t* sB, const float* __restrict__ W, int t)
{
#pragma unroll
    for (int i = 0; i < 8; ++i) {
        int f = t + i * 256;              // kp = f>>5 (0..63), n4 = f&31
        int kp = f >> 5, n4 = f & 31;
        float4 w0 = __ldg((const float4*)W + (2 * kp) * 32 + n4);
        float4 w1 = __ldg((const float4*)W + (2 * kp + 1) * 32 + n4);
        float a0[4] = {w0.x, w0.y, w0.z, w0.w};
        float a1[4] = {w1.x, w1.y, w1.z, w1.w};
        int ks = kp >> 3;
        int slot = (kp >> 2) & 1;
        int lane_k = kp & 3;
#pragma unroll
        for (int e = 0; e < 4; ++e) {
            int n = 4 * n4 + e;
            int nt = n >> 3;
            int lane = (n & 7) * 4 + lane_k;
            uint32_t wrd;
            *(__half2*)&wrd = __floats2half2_rn(a0[e], a1[e]);
            sB[(ks * 16 + nt) * 66 + lane * 2 + slot] = wrd;
        }
    }
}

template <int NTERMS, bool HOUT>
__global__ void __launch_bounds__(256, 2) gemm_mma(
    const __half* __restrict__ A0, const float* __restrict__ W0,
    const __half* __restrict__ A1, const float* __restrict__ W1,
    const __half* __restrict__ A2, const float* __restrict__ W2,
    const float* __restrict__ bias0, const float* __restrict__ bias1,
    const float* __restrict__ lnw, const float* __restrict__ lnb,
    void* __restrict__ outp, int N)
{
    extern __shared__ char smem[];
    uint32_t* sA = (uint32_t*)(smem + SM_A);
    uint32_t* sB = (uint32_t*)(smem + SM_B);
    float2* sPart = (float2*)(smem + SM_PART);
    float2* sStat = (float2*)(smem + SM_STAT);
    float* sBias  = (float*)(smem + SM_BIAS);
    float* sLnw   = (float*)(smem + SM_LNW);
    float* sLnb   = (float*)(smem + SM_LNB);

    const int t = threadIdx.x;
    const int warp = t >> 5;
    const int lane = t & 31;
    const int wm = warp >> 2;     // 0..1  (M half)
    const int wn = warp & 3;      // 0..3  (N quarter)
    const int nodeBase = blockIdx.x * 128;

    if (t < 128) {
        float b = bias0 ? __ldg(bias0 + t) : 0.f;
        if (bias1) b += __ldg(bias1 + t);
        sBias[t] = b;
        sLnw[t] = __ldg(lnw + t);
        sLnb[t] = __ldg(lnb + t);
    }

    const __half* As[3] = {A0, A1, A2};
    const float*  Ws[3] = {W0, W1, W2};

    float acc[4][4][4];
#pragma unroll
    for (int a = 0; a < 4; ++a)
#pragma unroll
        for (int b = 0; b < 4; ++b)
#pragma unroll
            for (int c = 0; c < 4; ++c) acc[a][b][c] = 0.f;

    const uint4* sA4 = (const uint4*)sA;
    const uint2* sB2 = (const uint2*)sB;

#pragma unroll 1
    for (int term = 0; term < NTERMS; ++term) {
        if (term > 0) __syncthreads();    // all warps done reading previous tiles
        stage_A16(sA, As[term], nodeBase, N, t);
        stage_B16(sB, Ws[term], t);
        __syncthreads();

#pragma unroll 1
        for (int ks = 0; ks < 8; ++ks) {
            uint4 af[4];
            uint2 bf[4];
#pragma unroll
            for (int mt = 0; mt < 4; ++mt)
                af[mt] = sA4[ks * 257 + (wm * 4 + mt) * 32 + lane];
#pragma unroll
            for (int nt = 0; nt < 4; ++nt)
                bf[nt] = sB2[(ks * 16 + wn * 4 + nt) * 33 + lane];
#pragma unroll
            for (int mt = 0; mt < 4; ++mt)
#pragma unroll
                for (int nt = 0; nt < 4; ++nt)
                    MMA_F16(acc[mt][nt], af[mt], bf[nt]);
        }
    }

    // ---------------- epilogue: bias + LayerNorm + ReLU ----------------
#pragma unroll
    for (int mt = 0; mt < 4; ++mt) {
#pragma unroll
        for (int hi = 0; hi < 2; ++hi) {
            float s = 0.f, q = 0.f;
#pragma unroll
            for (int nt = 0; nt < 4; ++nt) {
#pragma unroll
                for (int e = 0; e < 2; ++e) {
                    int col = (wn * 4 + nt) * 8 + (lane & 3) * 2 + e;
                    float v = acc[mt][nt][hi * 2 + e] + sBias[col];
                    s += v; q += v * v;
                }
            }
            s += __shfl_xor_sync(0xffffffffu, s, 1);
            q += __shfl_xor_sync(0xffffffffu, q, 1);
            s += __shfl_xor_sync(0xffffffffu, s, 2);
            q += __shfl_xor_sync(0xffffffffu, q, 2);
            if ((lane & 3) == 0) {
                int row = (wm * 4 + mt) * 16 + hi * 8 + (lane >> 2);
                sPart[row * 4 + wn] = make_float2(s, q);
            }
        }
    }
    __syncthreads();
    if (t < 128) {
        float2 p0 = sPart[t * 4 + 0], p1 = sPart[t * 4 + 1];
        float2 p2 = sPart[t * 4 + 2], p3 = sPart[t * 4 + 3];
        float s = p0.x + p1.x + p2.x + p3.x;
        float q = p0.y + p1.y + p2.y + p3.y;
        float mu = s * (1.0f / C);
        float var = q * (1.0f / C) - mu * mu;
        sStat[t] = make_float2(mu, rsqrtf(var + 1e-5f));
    }
    __syncthreads();

#pragma unroll
    for (int mt = 0; mt < 4; ++mt) {
#pragma unroll
        for (int hi = 0; hi < 2; ++hi) {
            int row = (wm * 4 + mt) * 16 + hi * 8 + (lane >> 2);
            int node = nodeBase + row;
            if (node < N) {
                float2 st = sStat[row];
#pragma unroll
                for (int nt = 0; nt < 4; ++nt) {
                    int col = (wn * 4 + nt) * 8 + (lane & 3) * 2;
                    float v0 = acc[mt][nt][hi * 2 + 0] + sBias[col];
                    float v1 = acc[mt][nt][hi * 2 + 1] + sBias[col + 1];
                    float o0 = fmaxf((v0 - st.x) * st.y * sLnw[col]     + sLnb[col],     0.f);
                    float o1 = fmaxf((v1 - st.x) * st.y * sLnw[col + 1] + sLnb[col + 1], 0.f);
                    if (HOUT) {
                        __half* o = (__half*)outp + (size_t)node * C + col;
                        *(__half2*)o = __floats2half2_rn(o0, o1);
                    } else {
                        float* o = (float*)outp + (size_t)node * C + col;
                        *(float2*)o = make_float2(o0, o1);
                    }
                }
            }
        }
    }
}

// ---------------- host launcher (single stream) ----------------
extern "C" void kernel_launch(void* const* d_in, const int* in_sizes, int n_in,
                              void* d_out, int out_size)
{
    const float* x_user = (const float*)d_in[0];
    const float* x_item = (const float*)d_in[1];
    const int*   ei_ui  = (const int*)d_in[2];
    const int*   ei_iu  = (const int*)d_in[3];
    const int*   ei_uu  = (const int*)d_in[4];
    const float* Wl     = (const float*)d_in[5];
    const float* bl     = (const float*)d_in[6];
    const float* Wr     = (const float*)d_in[7];
    const float* ln_w   = (const float*)d_in[8];
    const float* ln_b   = (const float*)d_in[9];
    float* out = (float*)d_out;

    void *phu_, *phi_, *phxu_, *phxi_, *phagg_, *pcnt_, *pws_, *prp_, *pci_, *pcur_;
    void *pbs_, *pbo_;
    cudaGetSymbolAddress(&phu_, g_hu);
    cudaGetSymbolAddress(&phi_, g_hi);
    cudaGetSymbolAddress(&phxu_, g_hxu);
    cudaGetSymbolAddress(&phxi_, g_hxi);
    cudaGetSymbolAddress(&phagg_, g_hagg);
    cudaGetSymbolAddress(&pcnt_, g_cnt);
    cudaGetSymbolAddress(&pws_, g_wsum);
    cudaGetSymbolAddress(&prp_, g_rowptr);
    cudaGetSymbolAddress(&pci_, g_colidx);
    cudaGetSymbolAddress(&pcur_, g_cur);
    cudaGetSymbolAddress(&pbs_, g_bsum);
    cudaGetSymbolAddress(&pbo_, g_boff);
    __half* phu  = (__half*)phu_;
    __half* phi  = (__half*)phi_;
    __half* phxu = (__half*)phxu_;
    __half* phxi = (__half*)phxi_;
    __half* phagg = (__half*)phagg_;
    int*   pcnt = (int*)pcnt_;
    float* pws  = (float*)pws_;
    int*   prp  = (int*)prp_;
    int*   pci  = (int*)pci_;
    int*   pcur = (int*)pcur_;
    int*   pbs  = (int*)pbs_;
    int*   pbo  = (int*)pbo_;

    cudaFuncSetAttribute((const void*)gemm_mma<2, true>,
                         cudaFuncAttributeMaxDynamicSharedMemorySize, GEMM_SMEM);
    cudaFuncSetAttribute((const void*)gemm_mma<3, true>,
                         cudaFuncAttributeMaxDynamicSharedMemorySize, GEMM_SMEM);
    cudaFuncSetAttribute((const void*)gemm_mma<2, false>,
                         cudaFuncAttributeMaxDynamicSharedMemorySize, GEMM_SMEM);
    cudaFuncSetAttribute((const void*)gemm_mma<3, false>,
                         cudaFuncAttributeMaxDynamicSharedMemorySize, GEMM_SMEM);

    const int GATHER_BLOCKS = 4096;

    // prep: fp16 copies + zero cnt/cur, wsum
    cvt2h_zero_k<<<2048, 256>>>((const float4*)x_user, (const float4*)x_item,
                                (uint2*)phu, (uint2*)phi, (long)(NC / 4),
                                (int4*)pcnt, (int4*)pcur, (long)(3 * N_NODE) / 4);
    addW2_k<<<dim3((CC + 255) / 256, 2), 256>>>(Wr, pws, CC);

    // CSR build (parallel 3-phase scan)
    count3_k<<<dim3(1024, 3), 256>>>(ei_ui + NEDGE, ei_iu + NEDGE, ei_uu + NEDGE,
                                     pcnt, NEDGE);
    scanA_k<<<dim3(SNB, 3), 256>>>(pcnt, pbs);
    scanB_k<<<3, 128>>>(pbs, pbo, prp);
    scanC_k<<<dim3(SNB, 3), 256>>>(pcnt, pbo, prp);
    fill3_k<<<dim3(1024, 3), 256>>>(ei_ui, ei_iu, ei_uu, prp, pcur, pci, NEDGE);

    // ---------------- layer 0 ----------------
    gather3h_k<<<dim3(GATHER_BLOCKS, 3), 256>>>(phu, phi, phu, prp, pci, phagg, N_NODE);

    gemm_mma<2, true><<<GEMM_GRID, 256, GEMM_SMEM>>>(
        phagg + 0 * NC, Wl + 0 * CC,
        phi,            Wr + 0 * CC,
        nullptr,        nullptr,
        bl + 0 * C, nullptr, ln_w + 1 * C, ln_b + 1 * C,
        phxi, N_NODE);

    gemm_mma<3, true><<<GEMM_GRID, 256, GEMM_SMEM>>>(
        phagg + 1 * NC, Wl + 1 * CC,
        phagg + 2 * NC, Wl + 2 * CC,
        phu,            pws + 0 * CC,
        bl + 1 * C, bl + 2 * C, ln_w + 0 * C, ln_b + 0 * C,
        phxu, N_NODE);

    // ---------------- layer 1 ----------------
    gather3h_k<<<dim3(GATHER_BLOCKS, 3), 256>>>(phxu, phxi, phxu, prp, pci, phagg, N_NODE);

    gemm_mma<2, false><<<GEMM_GRID, 256, GEMM_SMEM>>>(
        phagg + 0 * NC, Wl + (size_t)(1 * 3 + 0) * CC,
        phxi,           Wr + (size_t)(1 * 3 + 0) * CC,
        nullptr,        nullptr,
        bl + (size_t)(1 * 3 + 0) * C, nullptr,
        ln_w + (size_t)(1 * 2 + 1) * C, ln_b + (size_t)(1 * 2 + 1) * C,
        out + NC, N_NODE);

    gemm_mma<3, false><<<GEMM_GRID, 256, GEMM_SMEM>>>(
        phagg + 1 * NC, Wl + (size_t)(1 * 3 + 1) * CC,
        phagg + 2 * NC, Wl + (size_t)(1 * 3 + 2) * CC,
        phxu,           pws + 1 * CC,
        bl + (size_t)(1 * 3 + 1) * C, bl + (size_t)(1 * 3 + 2) * C,
        ln_w + (size_t)(1 * 2 + 0) * C, ln_b + (size_t)(1 * 2 + 0) * C,
        out, N_NODE);
}